// round 3
// baseline (speedup 1.0000x reference)
#include <cuda_runtime.h>
#include <cuda_bf16.h>
#include <cstddef>

// EncoderSelfAttention baseline: fp32 register-blocked SGEMM pipeline.
// B=2, C=512, N=4096.
//   q/k/v = W*x + b        (gemm<LTA=1,LTB=0>, M=512,N=4096,K=512), q scaled by 1/sqrt(C)
//   S = Q^T K              (gemm<0,0>, M=N=4096, K=512)  [both operands k-major: direct loads]
//   P = softmax(S)         (rowwise, 16 elems/thread in regs)
//   O = V P^T              (gemm<1,1>, M=512, N=4096, K=4096)
//   y = Wo*O + bo          (gemm<1,0>)

static constexpr int BDIM = 2;
static constexpr int CDIM = 512;
static constexpr int NTOK = 4096;
static constexpr long long CN = (long long)CDIM * NTOK;     // 2097152
static constexpr long long NN = (long long)NTOK * NTOK;     // 16777216

// Scratch (allocation-free rule: module-scope device arrays)
__device__ float g_q[BDIM * CDIM * NTOK];
__device__ float g_k[BDIM * CDIM * NTOK];
__device__ float g_v[BDIM * CDIM * NTOK];
__device__ float g_o[BDIM * CDIM * NTOK];
__device__ float g_s[BDIM * (long long)NTOK * NTOK];

// ---------------------------------------------------------------------------
// Generic tiled SGEMM: C[m][n] = alpha * (sum_k A(k,m)*B(k,n) + bias[m])
//   LTA=false: A stored [K][M] row-major (k-major, direct tile copy)
//   LTA=true : A stored [M][K] row-major (transpose on smem load)
//   (same for B with N)
// All dims assumed multiples of tile sizes (true for this problem).
// ---------------------------------------------------------------------------
template<bool LTA, bool LTB>
__global__ __launch_bounds__(256)
void gemm_kernel(const float* __restrict__ A, const float* __restrict__ B,
                 float* __restrict__ C, int M, int N, int K,
                 long long sA, long long sB, long long sC,
                 const float* __restrict__ bias, float alpha)
{
    constexpr int BM = 128, BN = 128, BK = 16;
    __shared__ float As[BK][BM + 4];
    __shared__ float Bs[BK][BN + 4];

    const int tid = threadIdx.x;
    const int tx = tid & 15;        // 0..15 -> N direction
    const int ty = tid >> 4;        // 0..15 -> M direction
    const int bm = blockIdx.y;
    const int bn = blockIdx.x;

    A += (size_t)blockIdx.z * sA;
    B += (size_t)blockIdx.z * sB;
    C += (size_t)blockIdx.z * sC;

    const int ldA = LTA ? K : M;
    const int ldB = LTB ? K : N;

    float acc[8][8];
#pragma unroll
    for (int i = 0; i < 8; ++i)
#pragma unroll
        for (int j = 0; j < 8; ++j) acc[i][j] = 0.f;

    for (int k0 = 0; k0 < K; k0 += BK) {
#pragma unroll
        for (int i = 0; i < 2; ++i) {
            const int id = tid + i * 256;          // 0..511 (512 float4 per tile)
            // ---- A tile ----
            if (LTA) {
                const int kc  = (id & 3) * 4;
                const int row = id >> 2;           // 0..127
                const float4 v = *(const float4*)(A + (size_t)(bm * BM + row) * ldA + k0 + kc);
                As[kc + 0][row] = v.x; As[kc + 1][row] = v.y;
                As[kc + 2][row] = v.z; As[kc + 3][row] = v.w;
            } else {
                const int col = (id & 31) * 4;     // 0..124
                const int row = id >> 5;           // 0..15
                *(float4*)&As[row][col] =
                    *(const float4*)(A + (size_t)(k0 + row) * ldA + bm * BM + col);
            }
            // ---- B tile ----
            if (LTB) {
                const int kc  = (id & 3) * 4;
                const int row = id >> 2;
                const float4 v = *(const float4*)(B + (size_t)(bn * BN + row) * ldB + k0 + kc);
                Bs[kc + 0][row] = v.x; Bs[kc + 1][row] = v.y;
                Bs[kc + 2][row] = v.z; Bs[kc + 3][row] = v.w;
            } else {
                const int col = (id & 31) * 4;
                const int row = id >> 5;
                *(float4*)&Bs[row][col] =
                    *(const float4*)(B + (size_t)(k0 + row) * ldB + bn * BN + col);
            }
        }
        __syncthreads();

#pragma unroll
        for (int kk = 0; kk < BK; ++kk) {
            const float4 a0 = *(const float4*)&As[kk][ty * 4];
            const float4 a1 = *(const float4*)&As[kk][64 + ty * 4];
            const float4 b0 = *(const float4*)&Bs[kk][tx * 4];
            const float4 b1 = *(const float4*)&Bs[kk][64 + tx * 4];
            const float a[8] = {a0.x, a0.y, a0.z, a0.w, a1.x, a1.y, a1.z, a1.w};
            const float b[8] = {b0.x, b0.y, b0.z, b0.w, b1.x, b1.y, b1.z, b1.w};
#pragma unroll
            for (int i = 0; i < 8; ++i)
#pragma unroll
                for (int j = 0; j < 8; ++j)
                    acc[i][j] = fmaf(a[i], b[j], acc[i][j]);
        }
        __syncthreads();
    }

#pragma unroll
    for (int i = 0; i < 8; ++i) {
        const int mloc = (i < 4) ? (ty * 4 + i) : (64 + ty * 4 + (i - 4));
        const int m = bm * BM + mloc;
        const float bv = bias ? bias[m] : 0.f;
        float4 o0, o1;
        o0.x = alpha * (acc[i][0] + bv); o0.y = alpha * (acc[i][1] + bv);
        o0.z = alpha * (acc[i][2] + bv); o0.w = alpha * (acc[i][3] + bv);
        o1.x = alpha * (acc[i][4] + bv); o1.y = alpha * (acc[i][5] + bv);
        o1.z = alpha * (acc[i][6] + bv); o1.w = alpha * (acc[i][7] + bv);
        *(float4*)(C + (size_t)m * N + bn * BN + tx * 4)      = o0;
        *(float4*)(C + (size_t)m * N + bn * BN + 64 + tx * 4) = o1;
    }
}

// ---------------------------------------------------------------------------
// Rowwise softmax over 4096 columns, in place. One block (256 thr) per row,
// 16 elements per thread held in registers (single read + single write).
// ---------------------------------------------------------------------------
__global__ __launch_bounds__(256)
void softmax_kernel(float* __restrict__ S)
{
    float* p = S + (size_t)blockIdx.x * NTOK;
    const int tid = threadIdx.x;
    __shared__ float red[8];

    float v[16];
    float mx = -3.4e38f;
#pragma unroll
    for (int j = 0; j < 16; ++j) {
        v[j] = p[tid + j * 256];
        mx = fmaxf(mx, v[j]);
    }
#pragma unroll
    for (int o = 16; o; o >>= 1) mx = fmaxf(mx, __shfl_xor_sync(0xffffffffu, mx, o));
    if ((tid & 31) == 0) red[tid >> 5] = mx;
    __syncthreads();
    mx = red[0];
#pragma unroll
    for (int w = 1; w < 8; ++w) mx = fmaxf(mx, red[w]);

    float sum = 0.f;
#pragma unroll
    for (int j = 0; j < 16; ++j) {
        v[j] = __expf(v[j] - mx);
        sum += v[j];
    }
#pragma unroll
    for (int o = 16; o; o >>= 1) sum += __shfl_xor_sync(0xffffffffu, sum, o);
    __syncthreads();
    if ((tid & 31) == 0) red[tid >> 5] = sum;
    __syncthreads();
    float tot = 0.f;
#pragma unroll
    for (int w = 0; w < 8; ++w) tot += red[w];

    const float inv = 1.0f / tot;
#pragma unroll
    for (int j = 0; j < 16; ++j) p[tid + j * 256] = v[j] * inv;
}

// ---------------------------------------------------------------------------

extern "C" void kernel_launch(void* const* d_in, const int* in_sizes, int n_in,
                              void* d_out, int out_size)
{
    const float* x  = (const float*)d_in[0];
    const float* wq = (const float*)d_in[1];
    const float* bq = (const float*)d_in[2];
    const float* wk = (const float*)d_in[3];
    const float* bk = (const float*)d_in[4];
    const float* wv = (const float*)d_in[5];
    const float* bv = (const float*)d_in[6];
    const float* wo = (const float*)d_in[7];
    const float* bo = (const float*)d_in[8];
    float* out = (float*)d_out;

    float *q, *k, *v, *o, *s;
    cudaGetSymbolAddress((void**)&q, g_q);
    cudaGetSymbolAddress((void**)&k, g_k);
    cudaGetSymbolAddress((void**)&v, g_v);
    cudaGetSymbolAddress((void**)&o, g_o);
    cudaGetSymbolAddress((void**)&s, g_s);

    const float scale = 0.044194173824159216f;  // 1/sqrt(512)
    const dim3 blk(256);
    const dim3 gProj(NTOK / 128, CDIM / 128, BDIM);   // 32 x 4 x 2
    const dim3 gScore(NTOK / 128, NTOK / 128, BDIM);  // 32 x 32 x 2

    // Projections: q (scaled), k, v
    gemm_kernel<true,  false><<<gProj, blk>>>(wq, x, q, CDIM, NTOK, CDIM, 0, CN, CN, bq, scale);
    gemm_kernel<true,  false><<<gProj, blk>>>(wk, x, k, CDIM, NTOK, CDIM, 0, CN, CN, bk, 1.0f);
    gemm_kernel<true,  false><<<gProj, blk>>>(wv, x, v, CDIM, NTOK, CDIM, 0, CN, CN, bv, 1.0f);

    // Scores: S[n][m] = sum_c q[c][n] * k[c][m]   (scale already folded into q)
    gemm_kernel<false, false><<<gScore, blk>>>(q, k, s, NTOK, NTOK, CDIM, CN, CN, NN, nullptr, 1.0f);

    // Softmax over last dim, in place
    softmax_kernel<<<BDIM * NTOK, blk>>>(s);

    // O[c][n] = sum_m v[c][m] * P[n][m]
    gemm_kernel<true,  true ><<<gProj, blk>>>(v, s, o, CDIM, NTOK, NTOK, CN, NN, CN, nullptr, 1.0f);

    // y = Wo * O + bo
    gemm_kernel<true,  false><<<gProj, blk>>>(wo, o, out, CDIM, NTOK, CDIM, 0, CN, CN, bo, 1.0f);
}

// round 8
// speedup vs baseline: 2.4231x; 2.4231x over previous
#include <cuda_runtime.h>
#include <cstdint>
#include <cstddef>

// EncoderSelfAttention, tf32 mma.sync pipeline (sm_103-safe: no tcgen05).
// B=2, C=512, N=4096.  All GEMMs K-major SS:  D[M,N] = A[M,:K] . B[N,:K]^T
//   Xt = rne(X^T)                       [n,c]
//   Qt = rne(s*(Xt.Wq^T + bq))          [n,c]
//   Kt = rne(Xt.Wk^T + bk)              [n,c]
//   Vt = rne(Xt.Wv^T + bv) ; Vc = Vt^T  [c,n]
//   S  = Qt.Kt^T ; P = rne(softmax(S))  [n,m]
//   Ot = rne(P.Vc^T)                    [n,c]
//   y  = Wo.Ot^T + bo                   [c,n]

static constexpr int BDIM = 2, CDIM = 512, NTOK = 4096;
static constexpr long long CN = (long long)CDIM * NTOK;
static constexpr long long NN = (long long)NTOK * NTOK;

__device__ float g_xt[BDIM * NTOK * CDIM];
__device__ float g_q [BDIM * NTOK * CDIM];
__device__ float g_k [BDIM * NTOK * CDIM];
__device__ float g_vt[BDIM * NTOK * CDIM];
__device__ float g_vc[BDIM * CDIM * NTOK];
__device__ float g_o [BDIM * NTOK * CDIM];
__device__ float g_s [BDIM * NN];
__device__ float g_w [4][CDIM * CDIM];

// ---------------------------------------------------------------- helpers
__device__ __forceinline__ float rne_tf32(float x) {
    float r; asm("cvt.rna.tf32.f32 %0, %1;" : "=f"(r) : "f"(x)); return r;
}
__device__ __forceinline__ uint32_t smem_u32(const void* p) {
    uint32_t a;
    asm("{ .reg .u64 t; cvta.to.shared.u64 t, %1; cvt.u32.u64 %0, t; }" : "=r"(a) : "l"(p));
    return a;
}
#define CP_COMMIT() asm volatile("cp.async.commit_group;" ::: "memory")
#define CP_WAIT(n)  asm volatile("cp.async.wait_group %0;" :: "n"(n) : "memory")
__device__ __forceinline__ void cp16(uint32_t dst, const void* src) {
    asm volatile("cp.async.cg.shared.global [%0], [%1], 16;" :: "r"(dst), "l"(src) : "memory");
}
// D += A(16x8) * B(8x8)^T, tf32. Fragment k-slots {c,c+4} hold original k {2c,2c+1},
// applied identically to A and B (k-permutation is GEMM-invariant).
__device__ __forceinline__ void mma16n8k8(float* d, float2 a_lo, float2 a_hi, float2 b) {
    asm volatile(
        "mma.sync.aligned.m16n8k8.row.col.f32.tf32.tf32.f32 "
        "{%0,%1,%2,%3},{%4,%5,%6,%7},{%8,%9},{%0,%1,%2,%3};"
        : "+f"(d[0]), "+f"(d[1]), "+f"(d[2]), "+f"(d[3])
        : "r"(__float_as_uint(a_lo.x)), "r"(__float_as_uint(a_hi.x)),
          "r"(__float_as_uint(a_lo.y)), "r"(__float_as_uint(a_hi.y)),
          "r"(__float_as_uint(b.x)),  "r"(__float_as_uint(b.y)));
}

// ---------------------------------------------------------------- GEMM
// CTA tile 128x128, BK=32 (8 x 16B chunks per row). 8 warps = 2(M) x 4(N),
// warp tile 64x32. Smem rows are 32 floats; 16B chunks XOR-swizzled by (row&7).
static constexpr int STAGES = 4;
static constexpr int A_BY = 128 * 32 * 4;           // 16 KB
static constexpr int STG_BY = 2 * A_BY;             // 32 KB
static constexpr int SMEM_TOTAL = STAGES * STG_BY;  // 128 KB

__device__ __forceinline__ int swz_idx(int r, int f) {   // word index in tile
    return r * 32 + ((((f >> 2) ^ (r & 7)) << 2) | (f & 3));
}

__global__ __launch_bounds__(256, 1)
void gemm_mma(const float* __restrict__ A, const float* __restrict__ B,
              float* __restrict__ C, int M, int N, int K,
              long long sA, long long sB, long long sC,
              const float* __restrict__ bias, int bias_mode,  // 0 none, 1 col, 2 row
              float alpha, int do_rne)
{
    extern __shared__ char smem[];
    const uint32_t sb = smem_u32(smem);
    const int tid = threadIdx.x, wid = tid >> 5, lane = tid & 31;
    const int wm = wid >> 2, wn = wid & 3;      // warp grid 2 x 4
    const int q = lane & 3, rg = lane >> 2;     // quad col, row-in-group
    const int bn = blockIdx.x, bm = blockIdx.y;

    A += (size_t)blockIdx.z * sA;
    B += (size_t)blockIdx.z * sB;
    C += (size_t)blockIdx.z * sC;
    const int lda = K, ldb = K, ldc = N;

    float acc[4][4][4];
#pragma unroll
    for (int i = 0; i < 4; ++i)
#pragma unroll
        for (int j = 0; j < 4; ++j)
#pragma unroll
            for (int e = 0; e < 4; ++e) acc[i][j][e] = 0.f;

    auto load_stage = [&](int st, int k0) {
        const uint32_t base = sb + st * STG_BY;
#pragma unroll
        for (int t = 0; t < 4; ++t) {           // A: 128 rows x 8 chunks
            const int id = tid + t * 256;
            const int r = id >> 3, ci = id & 7;
            cp16(base + ((r * 32 + (((ci ^ (r & 7)) << 2))) << 2),
                 A + (size_t)(bm * 128 + r) * lda + k0 + ci * 4);
        }
#pragma unroll
        for (int t = 0; t < 4; ++t) {           // B: 128 rows x 8 chunks
            const int id = tid + t * 256;
            const int r = id >> 3, ci = id & 7;
            cp16(base + A_BY + ((r * 32 + (((ci ^ (r & 7)) << 2))) << 2),
                 B + (size_t)(bn * 128 + r) * ldb + k0 + ci * 4);
        }
        CP_COMMIT();
    };

    const int nc = K / 32;
    load_stage(0, 0);
    load_stage(1, 32);
    load_stage(2, 64);

    for (int i = 0; i < nc; ++i) {
        CP_WAIT(2);
        __syncthreads();           // stage i ready; slot (i+3)&3 fully consumed at iter i-1
        if (i + 3 < nc) load_stage((i + 3) & 3, (i + 3) * 32);
        else CP_COMMIT();          // keep group counts aligned

        const float* As = (const float*)(smem + (i & 3) * STG_BY);
        const float* Bs = (const float*)(smem + (i & 3) * STG_BY + A_BY);
#pragma unroll
        for (int ks = 0; ks < 4; ++ks) {
            const int f = ks * 8 + 2 * q;
            float2 afr[4][2], bfr[4];
#pragma unroll
            for (int i2 = 0; i2 < 4; ++i2) {
                const int r0 = wm * 64 + i2 * 16 + rg;
                afr[i2][0] = *(const float2*)&As[swz_idx(r0,     f)];
                afr[i2][1] = *(const float2*)&As[swz_idx(r0 + 8, f)];
            }
#pragma unroll
            for (int j2 = 0; j2 < 4; ++j2)
                bfr[j2] = *(const float2*)&Bs[swz_idx(wn * 32 + j2 * 8 + rg, f)];
#pragma unroll
            for (int i2 = 0; i2 < 4; ++i2)
#pragma unroll
                for (int j2 = 0; j2 < 4; ++j2)
                    mma16n8k8(acc[i2][j2], afr[i2][0], afr[i2][1], bfr[j2]);
        }
    }
    __syncthreads();

    // Epilogue: c0,c1 -> (row, col..col+1); c2,c3 -> (row+8, col..col+1)
#pragma unroll
    for (int i2 = 0; i2 < 4; ++i2) {
#pragma unroll
        for (int j2 = 0; j2 < 4; ++j2) {
            const int row = bm * 128 + wm * 64 + i2 * 16 + rg;
            const int col = bn * 128 + wn * 32 + j2 * 8 + 2 * q;
            float b0 = 0.f, b1 = 0.f, b2 = 0.f, b3 = 0.f;
            if (bias_mode == 1) { b0 = bias[col]; b1 = bias[col + 1]; b2 = b0; b3 = b1; }
            else if (bias_mode == 2) { b0 = b1 = bias[row]; b2 = b3 = bias[row + 8]; }
            float v0 = alpha * (acc[i2][j2][0] + b0);
            float v1 = alpha * (acc[i2][j2][1] + b1);
            float v2 = alpha * (acc[i2][j2][2] + b2);
            float v3 = alpha * (acc[i2][j2][3] + b3);
            if (do_rne) { v0 = rne_tf32(v0); v1 = rne_tf32(v1); v2 = rne_tf32(v2); v3 = rne_tf32(v3); }
            *(float2*)&C[(size_t)row * ldc + col]       = make_float2(v0, v1);
            *(float2*)&C[(size_t)(row + 8) * ldc + col] = make_float2(v2, v3);
        }
    }
}

// ------------------------------------------------------- small helper kernels
__global__ __launch_bounds__(256)
void weights_rne(const float* w0, const float* w1, const float* w2, const float* w3,
                 float* o0, float* o1, float* o2, float* o3)
{
    const int i = blockIdx.x * 256 + threadIdx.x;
    o0[i] = rne_tf32(w0[i]); o1[i] = rne_tf32(w1[i]);
    o2[i] = rne_tf32(w2[i]); o3[i] = rne_tf32(w3[i]);
}

// in [R][Cc] -> out [Cc][R] with rne; grid (Cc/32, R/32, batch), block (32,8)
__global__ __launch_bounds__(256)
void transpose_rne(const float* __restrict__ in, float* __restrict__ out,
                   int R, int Cc, long long sIn, long long sOut)
{
    __shared__ float t[32][33];
    in  += (size_t)blockIdx.z * sIn;
    out += (size_t)blockIdx.z * sOut;
    const int tx = threadIdx.x, ty = threadIdx.y;
    const int c0 = blockIdx.x * 32, r0 = blockIdx.y * 32;
#pragma unroll
    for (int j = 0; j < 4; ++j)
        t[ty + j * 8][tx] = in[(size_t)(r0 + ty + j * 8) * Cc + c0 + tx];
    __syncthreads();
#pragma unroll
    for (int j = 0; j < 4; ++j)
        out[(size_t)(c0 + ty + j * 8) * R + r0 + tx] = rne_tf32(t[tx][ty + j * 8]);
}

__global__ __launch_bounds__(256)
void softmax_rne(float* __restrict__ S)
{
    float* p = S + (size_t)blockIdx.x * NTOK;
    const int tid = threadIdx.x;
    __shared__ float red[8];
    float v[16];
    float mx = -3.4e38f;
#pragma unroll
    for (int j = 0; j < 16; ++j) { v[j] = p[tid + j * 256]; mx = fmaxf(mx, v[j]); }
#pragma unroll
    for (int o = 16; o; o >>= 1) mx = fmaxf(mx, __shfl_xor_sync(~0u, mx, o));
    if ((tid & 31) == 0) red[tid >> 5] = mx;
    __syncthreads();
    mx = red[0];
#pragma unroll
    for (int w = 1; w < 8; ++w) mx = fmaxf(mx, red[w]);
    float sum = 0.f;
#pragma unroll
    for (int j = 0; j < 16; ++j) { v[j] = __expf(v[j] - mx); sum += v[j]; }
#pragma unroll
    for (int o = 16; o; o >>= 1) sum += __shfl_xor_sync(~0u, sum, o);
    __syncthreads();
    if ((tid & 31) == 0) red[tid >> 5] = sum;
    __syncthreads();
    float tot = 0.f;
#pragma unroll
    for (int w = 0; w < 8; ++w) tot += red[w];
    const float inv = 1.0f / tot;
#pragma unroll
    for (int j = 0; j < 16; ++j) p[tid + j * 256] = rne_tf32(v[j] * inv);
}

// -------------------------------------------------------------------- launch
extern "C" void kernel_launch(void* const* d_in, const int* in_sizes, int n_in,
                              void* d_out, int out_size)
{
    const float* x  = (const float*)d_in[0];
    const float* wq = (const float*)d_in[1];
    const float* bq = (const float*)d_in[2];
    const float* wk = (const float*)d_in[3];
    const float* bk = (const float*)d_in[4];
    const float* wv = (const float*)d_in[5];
    const float* bv = (const float*)d_in[6];
    const float* wo = (const float*)d_in[7];
    const float* bo = (const float*)d_in[8];
    float* out = (float*)d_out;

    float *xt, *q, *k, *vt, *vc, *o, *s, *w;
    cudaGetSymbolAddress((void**)&xt, g_xt);
    cudaGetSymbolAddress((void**)&q,  g_q);
    cudaGetSymbolAddress((void**)&k,  g_k);
    cudaGetSymbolAddress((void**)&vt, g_vt);
    cudaGetSymbolAddress((void**)&vc, g_vc);
    cudaGetSymbolAddress((void**)&o,  g_o);
    cudaGetSymbolAddress((void**)&s,  g_s);
    cudaGetSymbolAddress((void**)&w,  g_w);
    float* wqr = w, *wkr = w + CDIM * CDIM, *wvr = w + 2 * CDIM * CDIM, *wor = w + 3 * CDIM * CDIM;

    cudaFuncSetAttribute(gemm_mma, cudaFuncAttributeMaxDynamicSharedMemorySize, SMEM_TOTAL);

    const float scale = 0.044194173824159216f;  // 1/sqrt(512)

    weights_rne<<<CDIM * CDIM / 256, 256>>>(wq, wk, wv, wo, wqr, wkr, wvr, wor);
    transpose_rne<<<dim3(NTOK / 32, CDIM / 32, BDIM), dim3(32, 8)>>>(x, xt, CDIM, NTOK, CN, CN);

    const dim3 blk(256);
    const dim3 gP(CDIM / 128, NTOK / 128, BDIM);   // projections / PV: D = [4096, 512]
    const dim3 gS(NTOK / 128, NTOK / 128, BDIM);   // scores: D = [4096, 4096]
    const dim3 gY(NTOK / 128, CDIM / 128, BDIM);   // output: D = [512, 4096]

    gemm_mma<<<gP, blk, SMEM_TOTAL>>>(xt, wqr, q,  NTOK, CDIM, CDIM, CN, 0, CN, bq, 1, scale, 1);
    gemm_mma<<<gP, blk, SMEM_TOTAL>>>(xt, wkr, k,  NTOK, CDIM, CDIM, CN, 0, CN, bk, 1, 1.0f, 1);
    gemm_mma<<<gP, blk, SMEM_TOTAL>>>(xt, wvr, vt, NTOK, CDIM, CDIM, CN, 0, CN, bv, 1, 1.0f, 1);
    transpose_rne<<<dim3(CDIM / 32, NTOK / 32, BDIM), dim3(32, 8)>>>(vt, vc, NTOK, CDIM, CN, CN);

    gemm_mma<<<gS, blk, SMEM_TOTAL>>>(q, k, s, NTOK, NTOK, CDIM, CN, CN, NN, nullptr, 0, 1.0f, 0);
    softmax_rne<<<BDIM * NTOK, blk>>>(s);

    gemm_mma<<<gP, blk, SMEM_TOTAL>>>(s, vc, o, NTOK, CDIM, NTOK, NN, CN, CN, nullptr, 0, 1.0f, 1);
    gemm_mma<<<gY, blk, SMEM_TOTAL>>>(wor, o, out, CDIM, NTOK, CDIM, 0, CN, CN, bo, 2, 1.0f, 0);
}

// round 9
// speedup vs baseline: 2.9833x; 1.2312x over previous
#include <cuda_runtime.h>
#include <cstdint>
#include <cstddef>

// EncoderSelfAttention, tf32 mma.sync pipeline (sm_103-safe: no tcgen05).
// B=2, C=512, N=4096.  All GEMMs K-major SS:  D[M,N] = A[M,:K] . B[N,:K]^T
//   Xt = rne(X^T)                       [n,c]
//   Qt = rne(s*(Xt.Wq^T + bq))          [n,c]
//   Kt = rne(Xt.Wk^T + bk)              [n,c]
//   Vc = rne(Wv.Xt^T + bv)              [c,n]   (direct, no transpose kernel)
//   S  = Qt.Kt^T ; P = rne(softmax(S))  [n,m]
//   Ot = rne(P.Vc^T)                    [n,c]
//   y  = Wo.Ot^T + bo                   [c,n]

static constexpr int BDIM = 2, CDIM = 512, NTOK = 4096;
static constexpr long long CN = (long long)CDIM * NTOK;
static constexpr long long NN = (long long)NTOK * NTOK;

__device__ float g_xt[BDIM * NTOK * CDIM];
__device__ float g_q [BDIM * NTOK * CDIM];
__device__ float g_k [BDIM * NTOK * CDIM];
__device__ float g_vc[BDIM * CDIM * NTOK];
__device__ float g_o [BDIM * NTOK * CDIM];
__device__ float g_s [BDIM * NN];
__device__ float g_w [4][CDIM * CDIM];

// ---------------------------------------------------------------- helpers
__device__ __forceinline__ float rne_tf32(float x) {
    float r; asm("cvt.rna.tf32.f32 %0, %1;" : "=f"(r) : "f"(x)); return r;
}
__device__ __forceinline__ uint32_t smem_u32(const void* p) {
    uint32_t a;
    asm("{ .reg .u64 t; cvta.to.shared.u64 t, %1; cvt.u32.u64 %0, t; }" : "=r"(a) : "l"(p));
    return a;
}
#define CP_COMMIT() asm volatile("cp.async.commit_group;" ::: "memory")
#define CP_WAIT(n)  asm volatile("cp.async.wait_group %0;" :: "n"(n) : "memory")
__device__ __forceinline__ void cp16(uint32_t dst, const void* src) {
    asm volatile("cp.async.cg.shared.global [%0], [%1], 16;" :: "r"(dst), "l"(src) : "memory");
}
// D += A(16x8) * B(8x8)^T, tf32. Fragment k-slots {c,c+4} hold original k {2c,2c+1},
// applied identically to A and B (shared k-permutation is GEMM-invariant).
__device__ __forceinline__ void mma16n8k8(float* d, float2 a_lo, float2 a_hi, float2 b) {
    asm volatile(
        "mma.sync.aligned.m16n8k8.row.col.f32.tf32.tf32.f32 "
        "{%0,%1,%2,%3},{%4,%5,%6,%7},{%8,%9},{%0,%1,%2,%3};"
        : "+f"(d[0]), "+f"(d[1]), "+f"(d[2]), "+f"(d[3])
        : "r"(__float_as_uint(a_lo.x)), "r"(__float_as_uint(a_hi.x)),
          "r"(__float_as_uint(a_lo.y)), "r"(__float_as_uint(a_hi.y)),
          "r"(__float_as_uint(b.x)),  "r"(__float_as_uint(b.y)));
}

// ---------------------------------------------------------------- GEMM
// CTA tile 128(M) x 256(N), BK=32. 8 warps = 2(M) x 4(N), warp tile 64x64
// (32 MMAs per k-step vs 16 LDS.64). Smem rows: 32 floats (128B); 16B chunks
// XOR-swizzled by (row&7). Fragment addr over ks advances by pure XOR (ks<<5).
static constexpr int STAGES = 4;
static constexpr int A_BY = 128 * 32 * 4;           // 16 KB
static constexpr int B_BY = 256 * 32 * 4;           // 32 KB
static constexpr int STG_BY = A_BY + B_BY;          // 48 KB
static constexpr int SMEM_TOTAL = STAGES * STG_BY;  // 192 KB

__global__ __launch_bounds__(256, 1)
void gemm_mma(const float* __restrict__ A, const float* __restrict__ B,
              float* __restrict__ C, int M, int N, int K,
              long long sA, long long sB, long long sC,
              const float* __restrict__ bias, int bias_mode,  // 0 none, 1 col, 2 row
              float alpha, int do_rne)
{
    extern __shared__ char smem[];
    const uint32_t sb = smem_u32(smem);
    const int tid = threadIdx.x, wid = tid >> 5, lane = tid & 31;
    const int wm = wid >> 2, wn = wid & 3;      // warp grid 2(M) x 4(N)
    const int q = lane & 3, rg = lane >> 2;     // quad col, row-in-group
    const int q1 = q >> 1, q0 = q & 1;
    const int bn = blockIdx.x, bm = blockIdx.y;

    A += (size_t)blockIdx.z * sA;
    B += (size_t)blockIdx.z * sB;
    C += (size_t)blockIdx.z * sC;
    const int lda = K, ldb = K, ldc = N;

    float acc[4][8][4];
#pragma unroll
    for (int i = 0; i < 4; ++i)
#pragma unroll
        for (int j = 0; j < 8; ++j)
#pragma unroll
            for (int e = 0; e < 4; ++e) acc[i][j][e] = 0.f;

    // Per-thread fragment base byte offsets (ks = 0). Over ks: addr ^ (ks<<5).
    uint32_t aOff[4][2], bOff[8];
#pragma unroll
    for (int i2 = 0; i2 < 4; ++i2)
#pragma unroll
        for (int h = 0; h < 2; ++h) {
            const int r = wm * 64 + i2 * 16 + rg + h * 8;
            aOff[i2][h] = r * 128 + (((q1 ^ (r & 7))) << 4) + (q0 << 3);
        }
#pragma unroll
    for (int j2 = 0; j2 < 8; ++j2) {
        const int r = wn * 64 + j2 * 8 + rg;
        bOff[j2] = A_BY + r * 128 + (((q1 ^ (r & 7))) << 4) + (q0 << 3);
    }

    auto load_stage = [&](int st, int k0) {
        const uint32_t base = sb + st * STG_BY;
#pragma unroll
        for (int t = 0; t < 4; ++t) {           // A: 128 rows x 8 chunks
            const int id = tid + t * 256;
            const int r = id >> 3, ci = id & 7;
            cp16(base + r * 128 + ((ci ^ (r & 7)) << 4),
                 A + (size_t)(bm * 128 + r) * lda + k0 + ci * 4);
        }
#pragma unroll
        for (int t = 0; t < 8; ++t) {           // B: 256 rows x 8 chunks
            const int id = tid + t * 256;
            const int r = id >> 3, ci = id & 7;
            cp16(base + A_BY + r * 128 + ((ci ^ (r & 7)) << 4),
                 B + (size_t)(bn * 256 + r) * ldb + k0 + ci * 4);
        }
        CP_COMMIT();
    };

    const int nc = K / 32;
    load_stage(0, 0);
    load_stage(1, 32);
    load_stage(2, 64);

    for (int i = 0; i < nc; ++i) {
        CP_WAIT(2);
        __syncthreads();           // stage i ready; slot (i+3)&3 consumed at iter i-1
        if (i + 3 < nc) load_stage((i + 3) & 3, (i + 3) * 32);
        else CP_COMMIT();          // keep group counts aligned

        const uint32_t stg = (uint32_t)(i & 3) * STG_BY;
#pragma unroll
        for (int ks = 0; ks < 4; ++ks) {
            const uint32_t kx = (uint32_t)ks << 5;
            float2 afr[4][2], bfr[8];
#pragma unroll
            for (int i2 = 0; i2 < 4; ++i2) {
                afr[i2][0] = *(const float2*)&smem[(stg + aOff[i2][0]) ^ kx];
                afr[i2][1] = *(const float2*)&smem[(stg + aOff[i2][1]) ^ kx];
            }
#pragma unroll
            for (int j2 = 0; j2 < 8; ++j2)
                bfr[j2] = *(const float2*)&smem[(stg + bOff[j2]) ^ kx];
#pragma unroll
            for (int i2 = 0; i2 < 4; ++i2)
#pragma unroll
                for (int j2 = 0; j2 < 8; ++j2)
                    mma16n8k8(acc[i2][j2], afr[i2][0], afr[i2][1], bfr[j2]);
        }
    }

    // Epilogue: c0,c1 -> (row, col..col+1); c2,c3 -> (row+8, col..col+1)
#pragma unroll
    for (int i2 = 0; i2 < 4; ++i2) {
#pragma unroll
        for (int j2 = 0; j2 < 8; ++j2) {
            const int row = bm * 128 + wm * 64 + i2 * 16 + rg;
            const int col = bn * 256 + wn * 64 + j2 * 8 + 2 * q;
            float b0 = 0.f, b1 = 0.f, b2 = 0.f, b3 = 0.f;
            if (bias_mode == 1) { b0 = bias[col]; b1 = bias[col + 1]; b2 = b0; b3 = b1; }
            else if (bias_mode == 2) { b0 = b1 = bias[row]; b2 = b3 = bias[row + 8]; }
            float v0 = alpha * (acc[i2][j2][0] + b0);
            float v1 = alpha * (acc[i2][j2][1] + b1);
            float v2 = alpha * (acc[i2][j2][2] + b2);
            float v3 = alpha * (acc[i2][j2][3] + b3);
            if (do_rne) { v0 = rne_tf32(v0); v1 = rne_tf32(v1); v2 = rne_tf32(v2); v3 = rne_tf32(v3); }
            *(float2*)&C[(size_t)row * ldc + col]       = make_float2(v0, v1);
            *(float2*)&C[(size_t)(row + 8) * ldc + col] = make_float2(v2, v3);
        }
    }
}

// ------------------------------------------------------- small helper kernels
__global__ __launch_bounds__(256)
void weights_rne(const float* w0, const float* w1, const float* w2, const float* w3,
                 float* o0, float* o1, float* o2, float* o3)
{
    const int i = blockIdx.x * 256 + threadIdx.x;
    o0[i] = rne_tf32(w0[i]); o1[i] = rne_tf32(w1[i]);
    o2[i] = rne_tf32(w2[i]); o3[i] = rne_tf32(w3[i]);
}

// in [R][Cc] -> out [Cc][R] with rne; grid (Cc/32, R/32, batch), block (32,8)
__global__ __launch_bounds__(256)
void transpose_rne(const float* __restrict__ in, float* __restrict__ out,
                   int R, int Cc, long long sIn, long long sOut)
{
    __shared__ float t[32][33];
    in  += (size_t)blockIdx.z * sIn;
    out += (size_t)blockIdx.z * sOut;
    const int tx = threadIdx.x, ty = threadIdx.y;
    const int c0 = blockIdx.x * 32, r0 = blockIdx.y * 32;
#pragma unroll
    for (int j = 0; j < 4; ++j)
        t[ty + j * 8][tx] = in[(size_t)(r0 + ty + j * 8) * Cc + c0 + tx];
    __syncthreads();
#pragma unroll
    for (int j = 0; j < 4; ++j)
        out[(size_t)(c0 + ty + j * 8) * R + r0 + tx] = rne_tf32(t[tx][ty + j * 8]);
}

__global__ __launch_bounds__(256)
void softmax_rne(float* __restrict__ S)
{
    float4* p = (float4*)(S + (size_t)blockIdx.x * NTOK);
    const int tid = threadIdx.x;
    __shared__ float red[8];
    float4 v[4];
    float mx = -3.4e38f;
#pragma unroll
    for (int j = 0; j < 4; ++j) {
        v[j] = p[tid + j * 256];
        mx = fmaxf(mx, fmaxf(fmaxf(v[j].x, v[j].y), fmaxf(v[j].z, v[j].w)));
    }
#pragma unroll
    for (int o = 16; o; o >>= 1) mx = fmaxf(mx, __shfl_xor_sync(~0u, mx, o));
    if ((tid & 31) == 0) red[tid >> 5] = mx;
    __syncthreads();
    mx = red[0];
#pragma unroll
    for (int w = 1; w < 8; ++w) mx = fmaxf(mx, red[w]);
    float sum = 0.f;
#pragma unroll
    for (int j = 0; j < 4; ++j) {
        v[j].x = __expf(v[j].x - mx); v[j].y = __expf(v[j].y - mx);
        v[j].z = __expf(v[j].z - mx); v[j].w = __expf(v[j].w - mx);
        sum += (v[j].x + v[j].y) + (v[j].z + v[j].w);
    }
#pragma unroll
    for (int o = 16; o; o >>= 1) sum += __shfl_xor_sync(~0u, sum, o);
    __syncthreads();
    if ((tid & 31) == 0) red[tid >> 5] = sum;
    __syncthreads();
    float tot = 0.f;
#pragma unroll
    for (int w = 0; w < 8; ++w) tot += red[w];
    const float inv = 1.0f / tot;
#pragma unroll
    for (int j = 0; j < 4; ++j) {
        float4 o4;
        o4.x = rne_tf32(v[j].x * inv); o4.y = rne_tf32(v[j].y * inv);
        o4.z = rne_tf32(v[j].z * inv); o4.w = rne_tf32(v[j].w * inv);
        p[tid + j * 256] = o4;
    }
}

// -------------------------------------------------------------------- launch
extern "C" void kernel_launch(void* const* d_in, const int* in_sizes, int n_in,
                              void* d_out, int out_size)
{
    const float* x  = (const float*)d_in[0];
    const float* wq = (const float*)d_in[1];
    const float* bq = (const float*)d_in[2];
    const float* wk = (const float*)d_in[3];
    const float* bk = (const float*)d_in[4];
    const float* wv = (const float*)d_in[5];
    const float* bv = (const float*)d_in[6];
    const float* wo = (const float*)d_in[7];
    const float* bo = (const float*)d_in[8];
    float* out = (float*)d_out;

    float *xt, *q, *k, *vc, *o, *s, *w;
    cudaGetSymbolAddress((void**)&xt, g_xt);
    cudaGetSymbolAddress((void**)&q,  g_q);
    cudaGetSymbolAddress((void**)&k,  g_k);
    cudaGetSymbolAddress((void**)&vc, g_vc);
    cudaGetSymbolAddress((void**)&o,  g_o);
    cudaGetSymbolAddress((void**)&s,  g_s);
    cudaGetSymbolAddress((void**)&w,  g_w);
    float* wqr = w, *wkr = w + CDIM * CDIM, *wvr = w + 2 * CDIM * CDIM, *wor = w + 3 * CDIM * CDIM;

    cudaFuncSetAttribute(gemm_mma, cudaFuncAttributeMaxDynamicSharedMemorySize, SMEM_TOTAL);

    const float scale = 0.044194173824159216f;  // 1/sqrt(512)

    weights_rne<<<CDIM * CDIM / 256, 256>>>(wq, wk, wv, wo, wqr, wkr, wvr, wor);
    transpose_rne<<<dim3(NTOK / 32, CDIM / 32, BDIM), dim3(32, 8)>>>(x, xt, CDIM, NTOK, CN, CN);

    const dim3 blk(256);
    const dim3 gP(CDIM / 256, NTOK / 128, BDIM);   // (2, 32, 2)  D = [4096, 512]
    const dim3 gS(NTOK / 256, NTOK / 128, BDIM);   // (16, 32, 2) D = [4096, 4096]
    const dim3 gY(NTOK / 256, CDIM / 128, BDIM);   // (16, 4, 2)  D = [512, 4096]

    // Q, K projections: [n, c] layouts
    gemm_mma<<<gP, blk, SMEM_TOTAL>>>(xt, wqr, q, NTOK, CDIM, CDIM, CN, 0, CN, bq, 1, scale, 1);
    gemm_mma<<<gP, blk, SMEM_TOTAL>>>(xt, wkr, k, NTOK, CDIM, CDIM, CN, 0, CN, bk, 1, 1.0f, 1);
    // V projection directly in [c, n] layout: Vc = Wv . Xt^T + bv
    gemm_mma<<<gY, blk, SMEM_TOTAL>>>(wvr, xt, vc, CDIM, NTOK, CDIM, 0, CN, CN, bv, 2, 1.0f, 1);

    // Scores + softmax
    gemm_mma<<<gS, blk, SMEM_TOTAL>>>(q, k, s, NTOK, NTOK, CDIM, CN, CN, NN, nullptr, 0, 1.0f, 0);
    softmax_rne<<<BDIM * NTOK, blk>>>(s);

    // Ot = P . Vc^T  [n, c]
    gemm_mma<<<gP, blk, SMEM_TOTAL>>>(s, vc, o, NTOK, CDIM, NTOK, NN, CN, CN, nullptr, 0, 1.0f, 1);
    // y = Wo . Ot^T + bo  [c, n]
    gemm_mma<<<gY, blk, SMEM_TOTAL>>>(wor, o, out, CDIM, NTOK, CDIM, 0, CN, CN, bo, 2, 1.0f, 0);
}